// round 9
// baseline (speedup 1.0000x reference)
#include <cuda_runtime.h>

// Shapes (fixed):
//   image: (3, 512, 512) f32
//   x:     (16, 1, 512, 512) f32
//   W:     (9, 3, 3, 3) f32   b: (9,) f32
//   out:   (16, 1, 512, 512) f32
//
// Stage A: K[c,i,j] = b[c] + sum_{m,u,v} W[c,m,u,v]*image[m,i+u-1,j+v-1]
// Stage B: y[n,i,j] = sum_{u,v} x[n,i+u-1,j+v-1] * K[u*3+v,i,j]
// K (9 planes, 9.4 MB) is materialized in __device__ scratch (L2-resident).

#define HH 512
#define WW 512
#define NB 16
#define PLANE (HH * WW)

__device__ float Kscratch[9 * PLANE];   // 9.4 MB static device scratch

// ---------------------------------------------------------------------------
// Kernel A: per-pixel 3x3 kernels from the 3->9 channel conv. 2 px/thread.
// (unchanged from R7/R8 — measured 3.4 us)
// ---------------------------------------------------------------------------
__global__ __launch_bounds__(128)
void kernelK(const float* __restrict__ image,
             const float* __restrict__ Wt,
             const float* __restrict__ bb)
{
    __shared__ __align__(16) float Wsh[9 * 28];
    __shared__ float bsh[9];

    const int tx = threadIdx.x;          // 0..127
    for (int idx = tx; idx < 243; idx += 128) {
        int c = idx / 27;
        int t = idx % 27;
        Wsh[c * 28 + t] = Wt[idx];
    }
    if (tx < 9) bsh[tx] = bb[tx];
    __syncthreads();

    const int col0 = blockIdx.x * 256 + tx * 2;   // 2 px per thread
    const int i    = blockIdx.y;                  // row 0..511

    const bool rok0 = (i > 0);
    const bool rok2 = (i < HH - 1);
    const bool lok  = (col0 > 0);
    const bool rtok = (col0 < WW - 2);

    float win[3][3][4];   // [m][row][col], cols col0-1..col0+2
    const float* base = image + (size_t)i * WW + col0;
    #pragma unroll
    for (int m = 0; m < 3; m++) {
        const float* bm = base + (size_t)m * PLANE;
        #pragma unroll
        for (int u = 0; u < 3; u++) {
            const float* p = bm + (u - 1) * WW;
            bool rowok = (u == 1) ? true : (u == 0 ? rok0 : rok2);
            float2 v = make_float2(0.f, 0.f);
            if (rowok) v = *(const float2*)p;
            win[m][u][1] = v.x;
            win[m][u][2] = v.y;
            win[m][u][0] = (rowok && lok)  ? p[-1] : 0.f;
            win[m][u][3] = (rowok && rtok) ? p[2]  : 0.f;
        }
    }

    float* kout = Kscratch + (size_t)i * WW + col0;
    #pragma unroll
    for (int c = 0; c < 9; c++) {
        float4 wa = *(const float4*)&Wsh[c * 28 + 0];
        float4 wb = *(const float4*)&Wsh[c * 28 + 4];
        float4 wc = *(const float4*)&Wsh[c * 28 + 8];
        float4 wd = *(const float4*)&Wsh[c * 28 + 12];
        float4 we = *(const float4*)&Wsh[c * 28 + 16];
        float4 wf = *(const float4*)&Wsh[c * 28 + 20];
        float4 wg = *(const float4*)&Wsh[c * 28 + 24];
        float wv[27] = {wa.x, wa.y, wa.z, wa.w, wb.x, wb.y, wb.z, wb.w,
                        wc.x, wc.y, wc.z, wc.w, wd.x, wd.y, wd.z, wd.w,
                        we.x, we.y, we.z, we.w, wf.x, wf.y, wf.z, wf.w,
                        wg.x, wg.y, wg.z};
        float k0 = bsh[c], k1 = bsh[c];
        #pragma unroll
        for (int m = 0; m < 3; m++) {
            #pragma unroll
            for (int u = 0; u < 3; u++) {
                #pragma unroll
                for (int v = 0; v < 3; v++) {
                    float w = wv[m * 9 + u * 3 + v];
                    k0 = fmaf(w, win[m][u][v + 0], k0);
                    k1 = fmaf(w, win[m][u][v + 1], k1);
                }
            }
        }
        *(float2*)(kout + (size_t)c * PLANE) = make_float2(k0, k1);
    }
}

// ---------------------------------------------------------------------------
// Kernel B: apply per-pixel kernels. 4 px/thread (LDG.128 windows),
// 4 slices/block, 3-buffer rotation with prefetch distance 2.
// ---------------------------------------------------------------------------

// 6-wide row window [col0-1 .. col0+4], zero padded.
__device__ __forceinline__ void load_row6(const float* __restrict__ base,
                                          bool rowok, bool leftok, bool rightok,
                                          float r[6])
{
    if (rowok) {
        float4 v = *(const float4*)base;          // 16B aligned
        r[1] = v.x; r[2] = v.y; r[3] = v.z; r[4] = v.w;
        r[0] = leftok  ? base[-1] : 0.0f;
        r[5] = rightok ? base[4]  : 0.0f;
    } else {
        r[0] = r[1] = r[2] = r[3] = r[4] = r[5] = 0.0f;
    }
}

__device__ __forceinline__ void load_win3(const float* __restrict__ cbase,
                                          bool rok0, bool rok2,
                                          bool lok, bool rtok,
                                          float r[3][6])
{
    load_row6(cbase - WW, rok0, lok, rtok, r[0]);
    load_row6(cbase,      true, lok, rtok, r[1]);
    load_row6(cbase + WW, rok2, lok, rtok, r[2]);
}

__device__ __forceinline__ float4 apply_win(const float r[3][6], const float K[36])
{
    float a0 = 0.f, a1 = 0.f, a2 = 0.f, a3 = 0.f;
    #pragma unroll
    for (int u = 0; u < 3; u++) {
        #pragma unroll
        for (int v = 0; v < 3; v++) {
            const int c = u * 3 + v;
            a0 = fmaf(r[u][v + 0], K[c * 4 + 0], a0);
            a1 = fmaf(r[u][v + 1], K[c * 4 + 1], a1);
            a2 = fmaf(r[u][v + 2], K[c * 4 + 2], a2);
            a3 = fmaf(r[u][v + 3], K[c * 4 + 3], a3);
        }
    }
    float4 o; o.x = a0; o.y = a1; o.z = a2; o.w = a3;
    return o;
}

__global__ __launch_bounds__(128, 4)
void kernelApply(const float* __restrict__ x,
                 float* __restrict__ y)
{
    const int tx   = threadIdx.x;              // 0..127, block spans full row
    const int col0 = tx * 4;                   // 4 px per thread, 16B aligned
    const int i    = blockIdx.y;               // row
    const int n0   = blockIdx.z * 4;           // slice group of 4

    const bool rok0 = (i > 0);
    const bool rok2 = (i < HH - 1);
    const bool lok  = (tx > 0);
    const bool rtok = (tx < 127);

    const float* xb = x + (size_t)n0 * PLANE + (size_t)i * WW + col0;
    float*       yb = y + (size_t)n0 * PLANE + (size_t)i * WW + col0;

    // Start x pipeline first: slices n0, n0+1 fly while K loads resolve.
    float Xw[3][3][6];
    load_win3(xb,         rok0, rok2, lok, rtok, Xw[0]);
    load_win3(xb + PLANE, rok0, rok2, lok, rtok, Xw[1]);

    // 9 kernel taps for the 4 pixels: 9x LDG.128, L2-resident from kernel A.
    float K[36];   // K[c*4 + p]
    {
        const float* kb = Kscratch + (size_t)i * WW + col0;
        #pragma unroll
        for (int c = 0; c < 9; c++) {
            float4 kv = *(const float4*)(kb + (size_t)c * PLANE);
            K[c * 4 + 0] = kv.x; K[c * 4 + 1] = kv.y;
            K[c * 4 + 2] = kv.z; K[c * 4 + 3] = kv.w;
        }
    }

    #pragma unroll
    for (int n = 0; n < 4; n++) {
        if (n + 2 < 4)   // prefetch distance 2
            load_win3(xb + (size_t)(n + 2) * PLANE, rok0, rok2, lok, rtok,
                      Xw[(n + 2) % 3]);

        *(float4*)(yb + (size_t)n * PLANE) = apply_win(Xw[n % 3], K);
    }
}

extern "C" void kernel_launch(void* const* d_in, const int* in_sizes, int n_in,
                              void* d_out, int out_size)
{
    const float* image = (const float*)d_in[0];   // 3*512*512
    const float* x     = (const float*)d_in[1];   // 16*512*512
    const float* Wt    = (const float*)d_in[2];   // 243
    const float* bb    = (const float*)d_in[3];   // 9
    float* y = (float*)d_out;                     // 16*512*512

    dim3 blockA(128);
    dim3 gridA(WW / 256, HH);        // (2, 512) = 1024 blocks
    kernelK<<<gridA, blockA>>>(image, Wt, bb);

    dim3 blockB(128);
    dim3 gridB(1, HH, NB / 4);       // (1, 512, 4) = 2048 blocks, 4 slices each
    kernelApply<<<gridB, blockB>>>(x, y);
}

// round 10
// speedup vs baseline: 1.2201x; 1.2201x over previous
#include <cuda_runtime.h>

// Shapes (fixed):
//   image: (3, 512, 512) f32
//   x:     (16, 1, 512, 512) f32
//   W:     (9, 3, 3, 3) f32   b: (9,) f32
//   out:   (16, 1, 512, 512) f32
//
// Stage A: K[c,i,j] = b[c] + sum_{m,u,v} W[c,m,u,v]*image[m,i+u-1,j+v-1]
// Stage B: y[n,i,j] = sum_{u,v} x[n,i+u-1,j+v-1] * K[u*3+v,i,j]
// K (9 planes, 9.4 MB) is materialized in __device__ scratch (L2-resident).

#define HH 512
#define WW 512
#define NB 16
#define PLANE (HH * WW)
#define FULLMASK 0xffffffffu

__device__ float Kscratch[9 * PLANE];   // 9.4 MB static device scratch

// ---------------------------------------------------------------------------
// Kernel A: per-pixel 3x3 kernels from the 3->9 channel conv. 2 px/thread.
// (unchanged — measured ~3.4 us)
// ---------------------------------------------------------------------------
__global__ __launch_bounds__(128)
void kernelK(const float* __restrict__ image,
             const float* __restrict__ Wt,
             const float* __restrict__ bb)
{
    __shared__ __align__(16) float Wsh[9 * 28];
    __shared__ float bsh[9];

    const int tx = threadIdx.x;          // 0..127
    for (int idx = tx; idx < 243; idx += 128) {
        int c = idx / 27;
        int t = idx % 27;
        Wsh[c * 28 + t] = Wt[idx];
    }
    if (tx < 9) bsh[tx] = bb[tx];
    __syncthreads();

    const int col0 = blockIdx.x * 256 + tx * 2;   // 2 px per thread
    const int i    = blockIdx.y;                  // row 0..511

    const bool rok0 = (i > 0);
    const bool rok2 = (i < HH - 1);
    const bool lok  = (col0 > 0);
    const bool rtok = (col0 < WW - 2);

    float win[3][3][4];   // [m][row][col], cols col0-1..col0+2
    const float* base = image + (size_t)i * WW + col0;
    #pragma unroll
    for (int m = 0; m < 3; m++) {
        const float* bm = base + (size_t)m * PLANE;
        #pragma unroll
        for (int u = 0; u < 3; u++) {
            const float* p = bm + (u - 1) * WW;
            bool rowok = (u == 1) ? true : (u == 0 ? rok0 : rok2);
            float2 v = make_float2(0.f, 0.f);
            if (rowok) v = *(const float2*)p;
            win[m][u][1] = v.x;
            win[m][u][2] = v.y;
            win[m][u][0] = (rowok && lok)  ? p[-1] : 0.f;
            win[m][u][3] = (rowok && rtok) ? p[2]  : 0.f;
        }
    }

    float* kout = Kscratch + (size_t)i * WW + col0;
    #pragma unroll
    for (int c = 0; c < 9; c++) {
        float4 wa = *(const float4*)&Wsh[c * 28 + 0];
        float4 wb = *(const float4*)&Wsh[c * 28 + 4];
        float4 wc = *(const float4*)&Wsh[c * 28 + 8];
        float4 wd = *(const float4*)&Wsh[c * 28 + 12];
        float4 we = *(const float4*)&Wsh[c * 28 + 16];
        float4 wf = *(const float4*)&Wsh[c * 28 + 20];
        float4 wg = *(const float4*)&Wsh[c * 28 + 24];
        float wv[27] = {wa.x, wa.y, wa.z, wa.w, wb.x, wb.y, wb.z, wb.w,
                        wc.x, wc.y, wc.z, wc.w, wd.x, wd.y, wd.z, wd.w,
                        we.x, we.y, we.z, we.w, wf.x, wf.y, wf.z, wf.w,
                        wg.x, wg.y, wg.z};
        float k0 = bsh[c], k1 = bsh[c];
        #pragma unroll
        for (int m = 0; m < 3; m++) {
            #pragma unroll
            for (int u = 0; u < 3; u++) {
                #pragma unroll
                for (int v = 0; v < 3; v++) {
                    float w = wv[m * 9 + u * 3 + v];
                    k0 = fmaf(w, win[m][u][v + 0], k0);
                    k1 = fmaf(w, win[m][u][v + 1], k1);
                }
            }
        }
        *(float2*)(kout + (size_t)c * PLANE) = make_float2(k0, k1);
    }
}

// ---------------------------------------------------------------------------
// Kernel B: apply per-pixel kernels. 4 px/thread, block = full 512-px row,
// 8 slices/block, triple-buffered pipeline (dist 2), SHUFFLE halos:
// per row only 1 LDG.128 + 2 predicated single-lane edge LDGs.
// ---------------------------------------------------------------------------

struct Row4 {
    float4 v;        // cols col0..col0+3
    float  eL, eR;   // meaningful only in lane 0 / lane 31
};

__device__ __forceinline__ Row4 load_row4(const float* __restrict__ p,
                                          bool rowok, int lane, int tx)
{
    Row4 r;
    r.v  = make_float4(0.f, 0.f, 0.f, 0.f);
    if (rowok) r.v = *(const float4*)p;          // 16B aligned
    r.eL = 0.f;
    r.eR = 0.f;
    if (lane == 0  && rowok && tx != 0)   r.eL = p[-1];   // cross-warp left halo
    if (lane == 31 && rowok && tx != 127) r.eR = p[4];    // cross-warp right halo
    return r;
}

__device__ __forceinline__ void load_win(const float* __restrict__ cb,
                                         bool rok0, bool rok2, int lane, int tx,
                                         Row4 w[3])
{
    w[0] = load_row4(cb - WW, rok0, lane, tx);
    w[1] = load_row4(cb,      true, lane, tx);
    w[2] = load_row4(cb + WW, rok2, lane, tx);
}

// Expand a buffered row into the 6-wide window using register shuffles.
__device__ __forceinline__ void expand_row(const Row4& rw, int lane, float r[6])
{
    float sl = __shfl_up_sync(FULLMASK, rw.v.w, 1);     // neighbor's col+3
    float sr = __shfl_down_sync(FULLMASK, rw.v.x, 1);   // neighbor's col+0
    r[0] = (lane == 0)  ? rw.eL : sl;
    r[1] = rw.v.x; r[2] = rw.v.y; r[3] = rw.v.z; r[4] = rw.v.w;
    r[5] = (lane == 31) ? rw.eR : sr;
}

__device__ __forceinline__ float4 apply_win(const Row4 w[3], int lane,
                                            const float K[36])
{
    float a0 = 0.f, a1 = 0.f, a2 = 0.f, a3 = 0.f;
    #pragma unroll
    for (int u = 0; u < 3; u++) {
        float r[6];
        expand_row(w[u], lane, r);
        #pragma unroll
        for (int v = 0; v < 3; v++) {
            const int c = u * 3 + v;
            a0 = fmaf(r[v + 0], K[c * 4 + 0], a0);
            a1 = fmaf(r[v + 1], K[c * 4 + 1], a1);
            a2 = fmaf(r[v + 2], K[c * 4 + 2], a2);
            a3 = fmaf(r[v + 3], K[c * 4 + 3], a3);
        }
    }
    float4 o; o.x = a0; o.y = a1; o.z = a2; o.w = a3;
    return o;
}

__global__ __launch_bounds__(128, 4)
void kernelApply(const float* __restrict__ x,
                 float* __restrict__ y)
{
    const int tx   = threadIdx.x;              // 0..127, block = full row
    const int lane = tx & 31;
    const int col0 = tx * 4;                   // 4 px per thread, 16B aligned
    const int i    = blockIdx.y;               // row
    const int n0   = blockIdx.z * 8;           // 8 slices per block

    const bool rok0 = (i > 0);
    const bool rok2 = (i < HH - 1);

    const float* xb = x + (size_t)n0 * PLANE + (size_t)i * WW + col0;
    float*       yb = y + (size_t)n0 * PLANE + (size_t)i * WW + col0;

    // Start x pipeline first: slices n0, n0+1 in flight while K loads resolve.
    Row4 Xw[3][3];
    load_win(xb,         rok0, rok2, lane, tx, Xw[0]);
    load_win(xb + PLANE, rok0, rok2, lane, tx, Xw[1]);

    // 9 kernel taps for 4 pixels: 9x LDG.128, L2-resident from kernel A.
    float K[36];   // K[c*4 + p]
    {
        const float* kb = Kscratch + (size_t)i * WW + col0;
        #pragma unroll
        for (int c = 0; c < 9; c++) {
            float4 kv = *(const float4*)(kb + (size_t)c * PLANE);
            K[c * 4 + 0] = kv.x; K[c * 4 + 1] = kv.y;
            K[c * 4 + 2] = kv.z; K[c * 4 + 3] = kv.w;
        }
    }

    #pragma unroll
    for (int n = 0; n < 8; n++) {
        if (n + 2 < 8)   // prefetch distance 2
            load_win(xb + (size_t)(n + 2) * PLANE, rok0, rok2, lane, tx,
                     Xw[(n + 2) % 3]);

        *(float4*)(yb + (size_t)n * PLANE) = apply_win(Xw[n % 3], lane, K);
    }
}

extern "C" void kernel_launch(void* const* d_in, const int* in_sizes, int n_in,
                              void* d_out, int out_size)
{
    const float* image = (const float*)d_in[0];   // 3*512*512
    const float* x     = (const float*)d_in[1];   // 16*512*512
    const float* Wt    = (const float*)d_in[2];   // 243
    const float* bb    = (const float*)d_in[3];   // 9
    float* y = (float*)d_out;                     // 16*512*512

    dim3 blockA(128);
    dim3 gridA(WW / 256, HH);        // (2, 512) = 1024 blocks
    kernelK<<<gridA, blockA>>>(image, Wt, bb);

    dim3 blockB(128);
    dim3 gridB(1, HH, NB / 8);       // (1, 512, 2) = 1024 blocks, 8 slices each
    kernelApply<<<gridB, blockB>>>(x, y);
}

// round 11
// speedup vs baseline: 1.2912x; 1.0582x over previous
#include <cuda_runtime.h>

// Shapes (fixed):
//   image: (3, 512, 512) f32
//   x:     (16, 1, 512, 512) f32
//   W:     (9, 3, 3, 3) f32   b: (9,) f32
//   out:   (16, 1, 512, 512) f32
//
// Stage A: K[c,i,j] = b[c] + sum_{m,u,v} W[c,m,u,v]*image[m,i+u-1,j+v-1]
// Stage B: y[n,i,j] = sum_{u,v} x[n,i+u-1,j+v-1] * K[u*3+v,i,j]
// K (9 planes, 9.4 MB) is materialized in __device__ scratch (L2-resident).

#define HH 512
#define WW 512
#define NB 16
#define PLANE (HH * WW)
#define FULLMASK 0xffffffffu

__device__ float Kscratch[9 * PLANE];   // 9.4 MB static device scratch

// ---------------------------------------------------------------------------
// Kernel A: per-pixel 3x3 kernels from the 3->9 channel conv. 2 px/thread.
// (unchanged — measured ~3.4 us)
// ---------------------------------------------------------------------------
__global__ __launch_bounds__(128)
void kernelK(const float* __restrict__ image,
             const float* __restrict__ Wt,
             const float* __restrict__ bb)
{
    __shared__ __align__(16) float Wsh[9 * 28];
    __shared__ float bsh[9];

    const int tx = threadIdx.x;          // 0..127
    for (int idx = tx; idx < 243; idx += 128) {
        int c = idx / 27;
        int t = idx % 27;
        Wsh[c * 28 + t] = Wt[idx];
    }
    if (tx < 9) bsh[tx] = bb[tx];
    __syncthreads();

    const int col0 = blockIdx.x * 256 + tx * 2;   // 2 px per thread
    const int i    = blockIdx.y;                  // row 0..511

    const bool rok0 = (i > 0);
    const bool rok2 = (i < HH - 1);
    const bool lok  = (col0 > 0);
    const bool rtok = (col0 < WW - 2);

    float win[3][3][4];   // [m][row][col], cols col0-1..col0+2
    const float* base = image + (size_t)i * WW + col0;
    #pragma unroll
    for (int m = 0; m < 3; m++) {
        const float* bm = base + (size_t)m * PLANE;
        #pragma unroll
        for (int u = 0; u < 3; u++) {
            const float* p = bm + (u - 1) * WW;
            bool rowok = (u == 1) ? true : (u == 0 ? rok0 : rok2);
            float2 v = make_float2(0.f, 0.f);
            if (rowok) v = *(const float2*)p;
            win[m][u][1] = v.x;
            win[m][u][2] = v.y;
            win[m][u][0] = (rowok && lok)  ? p[-1] : 0.f;
            win[m][u][3] = (rowok && rtok) ? p[2]  : 0.f;
        }
    }

    float* kout = Kscratch + (size_t)i * WW + col0;
    #pragma unroll
    for (int c = 0; c < 9; c++) {
        float4 wa = *(const float4*)&Wsh[c * 28 + 0];
        float4 wb = *(const float4*)&Wsh[c * 28 + 4];
        float4 wc = *(const float4*)&Wsh[c * 28 + 8];
        float4 wd = *(const float4*)&Wsh[c * 28 + 12];
        float4 we = *(const float4*)&Wsh[c * 28 + 16];
        float4 wf = *(const float4*)&Wsh[c * 28 + 20];
        float4 wg = *(const float4*)&Wsh[c * 28 + 24];
        float wv[27] = {wa.x, wa.y, wa.z, wa.w, wb.x, wb.y, wb.z, wb.w,
                        wc.x, wc.y, wc.z, wc.w, wd.x, wd.y, wd.z, wd.w,
                        we.x, we.y, we.z, we.w, wf.x, wf.y, wf.z, wf.w,
                        wg.x, wg.y, wg.z};
        float k0 = bsh[c], k1 = bsh[c];
        #pragma unroll
        for (int m = 0; m < 3; m++) {
            #pragma unroll
            for (int u = 0; u < 3; u++) {
                #pragma unroll
                for (int v = 0; v < 3; v++) {
                    float w = wv[m * 9 + u * 3 + v];
                    k0 = fmaf(w, win[m][u][v + 0], k0);
                    k1 = fmaf(w, win[m][u][v + 1], k1);
                }
            }
        }
        *(float2*)(kout + (size_t)c * PLANE) = make_float2(k0, k1);
    }
}

// ---------------------------------------------------------------------------
// Kernel B: apply per-pixel kernels. 4 px/thread, block = full 512-px row,
// 8 slices/block. 4 float4-only buffers, prefetch distance 3, shuffle halos.
// Edge values loaded at use time by ONE 2-active-lane LDG per row (L1 hit).
// ---------------------------------------------------------------------------

__device__ __forceinline__ float4 ldrow4(const float* __restrict__ p, bool rowok)
{
    float4 v = make_float4(0.f, 0.f, 0.f, 0.f);
    if (rowok) v = *(const float4*)p;      // 16B aligned
    return v;
}

__device__ __forceinline__ void load_win(const float* __restrict__ cb,
                                         bool rok0, bool rok2, float4 w[3])
{
    w[0] = ldrow4(cb - WW, rok0);
    w[1] = ldrow4(cb,      true);
    w[2] = ldrow4(cb + WW, rok2);
}

__global__ __launch_bounds__(128, 5)
void kernelApply(const float* __restrict__ x,
                 float* __restrict__ y)
{
    const int tx   = threadIdx.x;              // 0..127, block = full row
    const int lane = tx & 31;
    const int col0 = tx * 4;                   // 4 px/thread, 16B aligned
    const int i    = blockIdx.y;               // row
    const int n0   = blockIdx.z * 8;           // 8 slices per block

    const bool rok0 = (i > 0);
    const bool rok2 = (i < HH - 1);
    // One LDG covers both warp-edge halos: lane 0 reads p[-1], lane 31 reads p[4].
    const bool eact = (lane == 0 && tx != 0) || (lane == 31 && tx != 127);
    const int  eoff = (lane == 0) ? -1 : 4;

    const float* xb = x + (size_t)n0 * PLANE + (size_t)i * WW + col0;
    float*       yb = y + (size_t)n0 * PLANE + (size_t)i * WW + col0;

    // ---- K loads FIRST (consumed first; L1tex FIFO order = need order) ----
    float K[36];   // K[c*4 + p]
    {
        const float* kb = Kscratch + (size_t)i * WW + col0;
        #pragma unroll
        for (int c = 0; c < 9; c++) {
            float4 kv = *(const float4*)(kb + (size_t)c * PLANE);
            K[c * 4 + 0] = kv.x; K[c * 4 + 1] = kv.y;
            K[c * 4 + 2] = kv.z; K[c * 4 + 3] = kv.w;
        }
    }

    // ---- preamble: slices 0,1,2 in flight (prefetch distance 3) ----
    float4 Xw[4][3];
    load_win(xb,             rok0, rok2, Xw[0]);
    load_win(xb + PLANE,     rok0, rok2, Xw[1]);
    load_win(xb + 2 * PLANE, rok0, rok2, Xw[2]);

    #pragma unroll
    for (int n = 0; n < 8; n++) {
        if (n + 3 < 8)
            load_win(xb + (size_t)(n + 3) * PLANE, rok0, rok2, Xw[(n + 3) & 3]);

        const float4* w = Xw[n & 3];
        const float*  p = xb + (size_t)n * PLANE;

        float a0 = 0.f, a1 = 0.f, a2 = 0.f, a3 = 0.f;
        #pragma unroll
        for (int u = 0; u < 3; u++) {
            const bool rowok = (u == 1) ? true : (u == 0 ? rok0 : rok2);
            // 2-active-lane edge load; line already L1-resident from the
            // neighboring thread's float4 prefetch 3 iterations ago.
            float e = 0.f;
            if (eact && rowok) e = p[(u - 1) * WW + eoff];

            const float4 v = w[u];
            float sl = __shfl_up_sync(FULLMASK, v.w, 1);
            float sr = __shfl_down_sync(FULLMASK, v.x, 1);
            float r0 = (lane == 0)  ? e : sl;
            float r5 = (lane == 31) ? e : sr;
            float r[6] = {r0, v.x, v.y, v.z, v.w, r5};

            #pragma unroll
            for (int vv = 0; vv < 3; vv++) {
                const int c = u * 3 + vv;
                a0 = fmaf(r[vv + 0], K[c * 4 + 0], a0);
                a1 = fmaf(r[vv + 1], K[c * 4 + 1], a1);
                a2 = fmaf(r[vv + 2], K[c * 4 + 2], a2);
                a3 = fmaf(r[vv + 3], K[c * 4 + 3], a3);
            }
        }
        float4 o; o.x = a0; o.y = a1; o.z = a2; o.w = a3;
        *(float4*)(yb + (size_t)n * PLANE) = o;
    }
}

extern "C" void kernel_launch(void* const* d_in, const int* in_sizes, int n_in,
                              void* d_out, int out_size)
{
    const float* image = (const float*)d_in[0];   // 3*512*512
    const float* x     = (const float*)d_in[1];   // 16*512*512
    const float* Wt    = (const float*)d_in[2];   // 243
    const float* bb    = (const float*)d_in[3];   // 9
    float* y = (float*)d_out;                     // 16*512*512

    dim3 blockA(128);
    dim3 gridA(WW / 256, HH);        // (2, 512) = 1024 blocks
    kernelK<<<gridA, blockA>>>(image, Wt, bb);

    dim3 blockB(128);
    dim3 gridB(1, HH, NB / 8);       // (1, 512, 2) = 1024 blocks, 8 slices each
    kernelApply<<<gridB, blockB>>>(x, y);
}